// round 16
// baseline (speedup 1.0000x reference)
#include <cuda_runtime.h>
#include <cuda_fp16.h>

#define B_ 8
#define C_ 32
#define H_ 256
#define W_ 256
#define FH_ 64
#define FW_ 64
#define P_ 25
#define HP_ 306   // H + 2*25

// Scratch: fp16 transposed input [B,H,W,C] (64B/pixel) + per-pixel coords
// (R11: padded 50.5MB tile regressed — dense 33MB tile + x-predication wins.
//  R14: launch_bounds(256,6) on gather regressed via spills — 48 regs / 5
//  blocks is the sweet spot; do NOT cap gather regs.
//  R15: identical gather source measured 60.4us vs R12's 42.1us with dur and
//  HBM rates both scaled 1.43x -> clock-state variance between holds, not a
//  kernel property. This round: clean re-measure of the same composition.)
__device__ __align__(128) __half g_tin_h[B_ * H_ * W_ * C_];
__device__ float g_coords[B_ * H_ * W_ * 2];

// XLA:GPU lowers f32 divide to div.full.f32 (~2 ulp). The resize 'src'
// coordinate src = i*63/255 is the ONE place where that rounding error is
// amplified: it survives (src - floor(src)) undamped and is then scaled by
// 152.5 into the sample position. Bit-match XLA's division here. (R3->R4:
// rel_err 1.76e-3 -> 1.24e-4.) DO NOT replace with __fdiv_rn or fast div.
__device__ __forceinline__ float div_full(float a, float b) {
    float r;
    asm("div.full.f32 %0, %1, %2;" : "=f"(r) : "f"(a), "f"(b));
    return r;
}

__device__ __forceinline__ void cubic_w(float t, float w[4]) {
    const float A = -0.75f;
    float x;
    x = t + 1.0f; w[0] = ((A * x - 5.0f * A) * x + 8.0f * A) * x - 4.0f * A;
    x = t;        w[1] = ((A + 2.0f) * x - (A + 3.0f)) * x * x + 1.0f;
    x = 1.0f - t; w[2] = ((A + 2.0f) * x - (A + 3.0f)) * x * x + 1.0f;
    x = 2.0f - t; w[3] = ((A * x - 5.0f * A) * x + 8.0f * A) * x - 4.0f * A;
}

// ---------------------------------------------------------------------------
// Kernel 1 (fused prep). Transpose: block = 2 rows x 32 w. Loads are LDG.128
// (float4); SMEM scatter is 4x STS.32 (R13: STS.128 at stride-33 rows is
// only 4B-aligned for odd c). Bank = (c + 4*f4 + e) mod 32 -> conflict-free.
// Stores are STG.128. Blocks [0, 8192): transpose; [8192, +2048): coords.
// ---------------------------------------------------------------------------
#define TR_BLOCKS_ (B_ * (H_ / 2) * (W_ / 32))    // 8192
#define CO_BLOCKS_ ((B_ * H_ * W_) / 256)         // 2048

__global__ __launch_bounds__(256) void prep_kernel(const float* __restrict__ inp,
                                                   const float* __restrict__ flow) {
    __shared__ float s2[2][32][33];
    int t = threadIdx.x;

    if (blockIdx.x < TR_BLOCKS_) {
        // ---- transpose part: 2 rows of 32 pixels, all 32 channels ----
        int bx = blockIdx.x;
        int w0 = (bx & 7) * 32;
        int h0 = ((bx >> 3) & 127) * 2;
        int b = bx >> 10;

        // phase 1: 512 float4 units, LDG.128 + 4x STS.32 each
#pragma unroll
        for (int r = 0; r < 2; r++) {
            int u = t + 256 * r;
            int f4 = u & 7;
            int c = (u >> 3) & 31;
            int hh = u >> 8;
            float4 v = *(const float4*)(inp + (((size_t)(b * C_ + c) * H_) + h0 + hh) * W_ + w0 + 4 * f4);
            s2[hh][c][4 * f4 + 0] = v.x;
            s2[hh][c][4 * f4 + 1] = v.y;
            s2[hh][c][4 * f4 + 2] = v.z;
            s2[hh][c][4 * f4 + 3] = v.w;
        }
        __syncthreads();

        // phase 2: 256 uint4 units; thread -> (row hh, pixel p, 8-ch group kg)
        // LDS bank = (8*kg + i + p) mod 32 distinct per warp for each i.
        // STG.128 at byte offset 64*pixel + 16*kg -> 16B-aligned.
        int hh = t >> 7;
        int p = (t >> 2) & 31;
        int kg = t & 3;
        float f0 = s2[hh][8 * kg + 0][p];
        float f1 = s2[hh][8 * kg + 1][p];
        float f2 = s2[hh][8 * kg + 2][p];
        float f3 = s2[hh][8 * kg + 3][p];
        float f4v = s2[hh][8 * kg + 4][p];
        float f5 = s2[hh][8 * kg + 5][p];
        float f6 = s2[hh][8 * kg + 6][p];
        float f7 = s2[hh][8 * kg + 7][p];
        __half2 h01 = __floats2half2_rn(f0, f1);
        __half2 h23 = __floats2half2_rn(f2, f3);
        __half2 h45 = __floats2half2_rn(f4v, f5);
        __half2 h67 = __floats2half2_rn(f6, f7);
        uint4 v;
        v.x = *(unsigned*)&h01;
        v.y = *(unsigned*)&h23;
        v.z = *(unsigned*)&h45;
        v.w = *(unsigned*)&h67;
        *(uint4*)(g_tin_h + ((size_t)((b * H_ + h0 + hh) * W_ + w0 + p)) * C_ + 8 * kg) = v;
    } else {
        // ---- coords part ----
        int idx = (blockIdx.x - TR_BLOCKS_) * 256 + t;
        int j = idx & (W_ - 1);
        int i = (idx >> 8) & (H_ - 1);
        int b = idx >> 16;

        float sy = div_full((float)i * (float)(FH_ - 1), (float)(H_ - 1));
        float sx = div_full((float)j * (float)(FW_ - 1), (float)(W_ - 1));
        float fy0 = floorf(sy), fx0 = floorf(sx);
        float ty = sy - fy0, tx = sx - fx0;   // exact (Sterbenz)
        int iy0 = (int)fy0, ix0 = (int)fx0;
        float wy[4], wx[4];
        cubic_w(ty, wy);
        cubic_w(tx, wx);

        const float* f0 = flow + b * 2 * FH_ * FW_;   // channel 0: x-flow
        const float* f1 = f0 + FH_ * FW_;             // channel 1: y-flow

        int ry[4], rx[4];
#pragma unroll
        for (int m = 0; m < 4; m++) {
            int y = iy0 - 1 + m; ry[m] = min(max(y, 0), FH_ - 1);
            int x = ix0 - 1 + m; rx[m] = min(max(x, 0), FW_ - 1);
        }
        float accx = 0.0f, accy = 0.0f;
#pragma unroll
        for (int m = 0; m < 4; m++) {
            int rb = ry[m] * FW_;
#pragma unroll
            for (int n = 0; n < 4; n++) {
                float w = wy[m] * wx[n];
                int o = rb + rx[n];
                accx += w * __ldg(&f0[o]);
                accy += w * __ldg(&f1[o]);
            }
        }

        float gx256 = -1.0f + j * (2.0f / (float)(W_ - 1));
        float gy256 = -1.0f + i * (2.0f / (float)(H_ - 1));
        float gx306 = -1.0f + (j + P_) * (2.0f / (float)(HP_ - 1));
        float gy306 = -1.0f + (i + P_) * (2.0f / (float)(HP_ - 1));
        float xp = (accx - gx256 + gx306 + 1.0f) * (0.5f * (float)(HP_ - 1));
        float yp = (accy - gy256 + gy306 + 1.0f) * (0.5f * (float)(HP_ - 1));

        g_coords[idx * 2 + 0] = xp;
        g_coords[idx * 2 + 1] = yp;
    }
}

// ---------------------------------------------------------------------------
// Kernel 2: gather — exact R12 configuration (plain launch_bounds(256),
// natural 48 regs / 5 blocks/SM). R14 proved capping regs to 40 spills and
// costs time; this config measured 42.1us on a clean hold (R12).
// ---------------------------------------------------------------------------
#define GPX_ 64   // pixels per block (8 warps * 8)
__global__ __launch_bounds__(256) void gather_kernel(float* __restrict__ out) {
    __shared__ float s[C_][GPX_ + 1];
    int b = blockIdx.z;
    int i = blockIdx.y;
    int j0 = blockIdx.x * GPX_;
    int warp = threadIdx.x >> 5;   // 0..7
    int lane = threadIdx.x & 31;
    int pix = lane >> 2;           // pixel-in-warp 0..7
    int lane4 = lane & 3;          // channel-quarter 0..3 (8 halfs each)
    int p = warp * 8 + pix;        // pixel-in-block 0..63
    int j = j0 + p;

    int pidx = ((b * H_) + i) * W_ + j;
    float xp = __ldg(&g_coords[pidx * 2 + 0]);
    float yp = __ldg(&g_coords[pidx * 2 + 1]);

    float fx = floorf(xp), fy = floorf(yp);
    float tx = xp - fx, ty = yp - fy;
    int ix = (int)fx, iy = (int)fy;

    float a0 = 0.f, a1 = 0.f, a2 = 0.f, a3 = 0.f;
    float a4 = 0.f, a5 = 0.f, a6 = 0.f, a7 = 0.f;

    bool dead = (iy + 2 < 0) | (iy - 1 >= HP_) | (ix + 2 < 0) | (ix - 1 >= HP_);
    if (!__all_sync(0xFFFFFFFFu, dead)) {
        float wx[4], wy[4];
        cubic_w(tx, wx);
        cubic_w(ty, wy);
        __half2 wxh[4];
#pragma unroll
        for (int n = 0; n < 4; n++) wxh[n] = __float2half2_rn(wx[n]);

        // hoisted x side: offsets + validity computed once per pixel
        int xoff[4];
        bool xval[4];
#pragma unroll
        for (int n = 0; n < 4; n++) {
            int xx = ix - 1 + n;
            xval[n] = ((unsigned)xx < (unsigned)HP_);
            int xs = min(max(xx - P_, 0), W_ - 1);
            xoff[n] = xs * C_;
        }

        const __half* base = g_tin_h + (size_t)b * (H_ * W_ * C_) + lane4 * 8;
#pragma unroll
        for (int m = 0; m < 4; m++) {
            int yy = iy - 1 + m;
            if ((unsigned)yy < (unsigned)HP_) {
                int ys = min(max(yy - P_, 0), H_ - 1);
                const __half* row = base + ys * (W_ * C_);
                uint4 v[4];
#pragma unroll
                for (int n = 0; n < 4; n++)
                    if (xval[n]) v[n] = __ldg((const uint4*)(row + xoff[n]));

                __half2 r0 = __float2half2_rn(0.f), r1 = r0, r2 = r0, r3 = r0;
#pragma unroll
                for (int n = 0; n < 4; n++) {
                    if (xval[n]) {
                        r0 = __hfma2(*(const __half2*)&v[n].x, wxh[n], r0);
                        r1 = __hfma2(*(const __half2*)&v[n].y, wxh[n], r1);
                        r2 = __hfma2(*(const __half2*)&v[n].z, wxh[n], r2);
                        r3 = __hfma2(*(const __half2*)&v[n].w, wxh[n], r3);
                    }
                }
                float wym = wy[m];
                float2 f01 = __half22float2(r0);
                float2 f23 = __half22float2(r1);
                float2 f45 = __half22float2(r2);
                float2 f67 = __half22float2(r3);
                a0 += wym * f01.x;  a1 += wym * f01.y;
                a2 += wym * f23.x;  a3 += wym * f23.y;
                a4 += wym * f45.x;  a5 += wym * f45.y;
                a6 += wym * f67.x;  a7 += wym * f67.y;
            }
        }
    }

    // s[channel][pixel]; write bank = 8*lane4 + k + pix (+8*warp) mod 32:
    // all 32 distinct -> conflict-free.
    float acc[8] = {a0, a1, a2, a3, a4, a5, a6, a7};
#pragma unroll
    for (int k = 0; k < 8; k++) s[8 * lane4 + k][p] = acc[k];
    __syncthreads();

    // warp w stores channels {w, w+8, w+16, w+24}: 64 contiguous floats each
    // (2 x 128B STG). Read bank = cc + q mod 32: conflict-free.
#pragma unroll
    for (int q = 0; q < 4; q++) {
        int cc = warp + q * 8;
        float* orow = out + (((b * C_ + cc) * H_) + i) * W_ + j0;
        orow[lane]      = s[cc][lane];
        orow[lane + 32] = s[cc][lane + 32];
    }
}

extern "C" void kernel_launch(void* const* d_in, const int* in_sizes, int n_in,
                              void* d_out, int out_size) {
    const float* input = (const float*)d_in[0];   // [8,32,256,256]
    const float* flow  = (const float*)d_in[1];   // [8,2,64,64]
    float* out = (float*)d_out;                   // [8,32,256,256]

    prep_kernel<<<TR_BLOCKS_ + CO_BLOCKS_, 256>>>(input, flow);
    {
        dim3 grid(W_ / GPX_, H_, B_);
        gather_kernel<<<grid, 256>>>(out);
    }
}

// round 17
// speedup vs baseline: 1.3191x; 1.3191x over previous
#include <cuda_runtime.h>
#include <cuda_fp16.h>

#define B_ 8
#define C_ 32
#define H_ 256
#define W_ 256
#define FH_ 64
#define FW_ 64
#define P_ 25
#define HP_ 306   // H + 2*25

// Scratch: fp16 transposed input [B,H,W,C] (64B/pixel) + per-pixel coords
// (R11: padded tile regressed; dense 33MB + x-predication wins.
//  R14: FORCED reg cap (launch_bounds .,6) spills -> regression. R17: reduce
//  live state instead (stage 2 uint4 not 4) so ptxas lands <=40 naturally.
//  R15/R16: fleet has ~1.44x clock-state split between holds; compare rounds
//  via clock-invariant metrics (regs/occ/pipe%/bytes), not wallclock.)
__device__ __align__(128) __half g_tin_h[B_ * H_ * W_ * C_];
__device__ float g_coords[B_ * H_ * W_ * 2];

// XLA:GPU lowers f32 divide to div.full.f32 (~2 ulp). The resize 'src'
// coordinate src = i*63/255 is the ONE place where that rounding error is
// amplified: it survives (src - floor(src)) undamped and is then scaled by
// 152.5 into the sample position. Bit-match XLA's division here. (R3->R4:
// rel_err 1.76e-3 -> 1.24e-4.) DO NOT replace with __fdiv_rn or fast div.
__device__ __forceinline__ float div_full(float a, float b) {
    float r;
    asm("div.full.f32 %0, %1, %2;" : "=f"(r) : "f"(a), "f"(b));
    return r;
}

__device__ __forceinline__ void cubic_w(float t, float w[4]) {
    const float A = -0.75f;
    float x;
    x = t + 1.0f; w[0] = ((A * x - 5.0f * A) * x + 8.0f * A) * x - 4.0f * A;
    x = t;        w[1] = ((A + 2.0f) * x - (A + 3.0f)) * x * x + 1.0f;
    x = 1.0f - t; w[2] = ((A + 2.0f) * x - (A + 3.0f)) * x * x + 1.0f;
    x = 2.0f - t; w[3] = ((A * x - 5.0f * A) * x + 8.0f * A) * x - 4.0f * A;
}

// ---------------------------------------------------------------------------
// Kernel 1 (fused prep). Transpose: block = 2 rows x 32 w. Loads are LDG.128
// (float4); SMEM scatter is 4x STS.32 (R13: STS.128 at stride-33 rows is
// only 4B-aligned for odd c). Bank = (c + 4*f4 + e) mod 32 -> conflict-free.
// Stores are STG.128. Blocks [0, 8192): transpose; [8192, +2048): coords.
// ---------------------------------------------------------------------------
#define TR_BLOCKS_ (B_ * (H_ / 2) * (W_ / 32))    // 8192
#define CO_BLOCKS_ ((B_ * H_ * W_) / 256)         // 2048

__global__ __launch_bounds__(256) void prep_kernel(const float* __restrict__ inp,
                                                   const float* __restrict__ flow) {
    __shared__ float s2[2][32][33];
    int t = threadIdx.x;

    if (blockIdx.x < TR_BLOCKS_) {
        // ---- transpose part: 2 rows of 32 pixels, all 32 channels ----
        int bx = blockIdx.x;
        int w0 = (bx & 7) * 32;
        int h0 = ((bx >> 3) & 127) * 2;
        int b = bx >> 10;

        // phase 1: 512 float4 units, LDG.128 + 4x STS.32 each
#pragma unroll
        for (int r = 0; r < 2; r++) {
            int u = t + 256 * r;
            int f4 = u & 7;
            int c = (u >> 3) & 31;
            int hh = u >> 8;
            float4 v = *(const float4*)(inp + (((size_t)(b * C_ + c) * H_) + h0 + hh) * W_ + w0 + 4 * f4);
            s2[hh][c][4 * f4 + 0] = v.x;
            s2[hh][c][4 * f4 + 1] = v.y;
            s2[hh][c][4 * f4 + 2] = v.z;
            s2[hh][c][4 * f4 + 3] = v.w;
        }
        __syncthreads();

        // phase 2: 256 uint4 units; thread -> (row hh, pixel p, 8-ch group kg)
        // LDS bank = (8*kg + i + p) mod 32 distinct per warp for each i.
        // STG.128 at byte offset 64*pixel + 16*kg -> 16B-aligned.
        int hh = t >> 7;
        int p = (t >> 2) & 31;
        int kg = t & 3;
        float f0 = s2[hh][8 * kg + 0][p];
        float f1 = s2[hh][8 * kg + 1][p];
        float f2 = s2[hh][8 * kg + 2][p];
        float f3 = s2[hh][8 * kg + 3][p];
        float f4v = s2[hh][8 * kg + 4][p];
        float f5 = s2[hh][8 * kg + 5][p];
        float f6 = s2[hh][8 * kg + 6][p];
        float f7 = s2[hh][8 * kg + 7][p];
        __half2 h01 = __floats2half2_rn(f0, f1);
        __half2 h23 = __floats2half2_rn(f2, f3);
        __half2 h45 = __floats2half2_rn(f4v, f5);
        __half2 h67 = __floats2half2_rn(f6, f7);
        uint4 v;
        v.x = *(unsigned*)&h01;
        v.y = *(unsigned*)&h23;
        v.z = *(unsigned*)&h45;
        v.w = *(unsigned*)&h67;
        *(uint4*)(g_tin_h + ((size_t)((b * H_ + h0 + hh) * W_ + w0 + p)) * C_ + 8 * kg) = v;
    } else {
        // ---- coords part ----
        int idx = (blockIdx.x - TR_BLOCKS_) * 256 + t;
        int j = idx & (W_ - 1);
        int i = (idx >> 8) & (H_ - 1);
        int b = idx >> 16;

        float sy = div_full((float)i * (float)(FH_ - 1), (float)(H_ - 1));
        float sx = div_full((float)j * (float)(FW_ - 1), (float)(W_ - 1));
        float fy0 = floorf(sy), fx0 = floorf(sx);
        float ty = sy - fy0, tx = sx - fx0;   // exact (Sterbenz)
        int iy0 = (int)fy0, ix0 = (int)fx0;
        float wy[4], wx[4];
        cubic_w(ty, wy);
        cubic_w(tx, wx);

        const float* f0 = flow + b * 2 * FH_ * FW_;   // channel 0: x-flow
        const float* f1 = f0 + FH_ * FW_;             // channel 1: y-flow

        int ry[4], rx[4];
#pragma unroll
        for (int m = 0; m < 4; m++) {
            int y = iy0 - 1 + m; ry[m] = min(max(y, 0), FH_ - 1);
            int x = ix0 - 1 + m; rx[m] = min(max(x, 0), FW_ - 1);
        }
        float accx = 0.0f, accy = 0.0f;
#pragma unroll
        for (int m = 0; m < 4; m++) {
            int rb = ry[m] * FW_;
#pragma unroll
            for (int n = 0; n < 4; n++) {
                float w = wy[m] * wx[n];
                int o = rb + rx[n];
                accx += w * __ldg(&f0[o]);
                accy += w * __ldg(&f1[o]);
            }
        }

        float gx256 = -1.0f + j * (2.0f / (float)(W_ - 1));
        float gy256 = -1.0f + i * (2.0f / (float)(H_ - 1));
        float gx306 = -1.0f + (j + P_) * (2.0f / (float)(HP_ - 1));
        float gy306 = -1.0f + (i + P_) * (2.0f / (float)(HP_ - 1));
        float xp = (accx - gx256 + gx306 + 1.0f) * (0.5f * (float)(HP_ - 1));
        float yp = (accy - gy256 + gy306 + 1.0f) * (0.5f * (float)(HP_ - 1));

        g_coords[idx * 2 + 0] = xp;
        g_coords[idx * 2 + 1] = yp;
    }
}

// ---------------------------------------------------------------------------
// Kernel 2: gather. R17: inner row loop stages 2 uint4 at a time (taps 0-1,
// FMA, taps 2-3, FMA) instead of all 4 -> ~8 fewer live regs; goal is a
// NATURAL allocation <=40 regs -> 6 blocks/SM (75% occ) with zero spills
// (R14 showed forced capping spills). FMA order n=0..3 unchanged -> output
// bit-identical (rel_err must stay 4.383332e-4).
// ---------------------------------------------------------------------------
#define GPX_ 64   // pixels per block (8 warps * 8)
__global__ __launch_bounds__(256) void gather_kernel(float* __restrict__ out) {
    __shared__ float s[C_][GPX_ + 1];
    int b = blockIdx.z;
    int i = blockIdx.y;
    int j0 = blockIdx.x * GPX_;
    int warp = threadIdx.x >> 5;   // 0..7
    int lane = threadIdx.x & 31;
    int pix = lane >> 2;           // pixel-in-warp 0..7
    int lane4 = lane & 3;          // channel-quarter 0..3 (8 halfs each)
    int p = warp * 8 + pix;        // pixel-in-block 0..63
    int j = j0 + p;

    int pidx = ((b * H_) + i) * W_ + j;
    float xp = __ldg(&g_coords[pidx * 2 + 0]);
    float yp = __ldg(&g_coords[pidx * 2 + 1]);

    float fx = floorf(xp), fy = floorf(yp);
    float tx = xp - fx, ty = yp - fy;
    int ix = (int)fx, iy = (int)fy;

    float a0 = 0.f, a1 = 0.f, a2 = 0.f, a3 = 0.f;
    float a4 = 0.f, a5 = 0.f, a6 = 0.f, a7 = 0.f;

    bool dead = (iy + 2 < 0) | (iy - 1 >= HP_) | (ix + 2 < 0) | (ix - 1 >= HP_);
    if (!__all_sync(0xFFFFFFFFu, dead)) {
        float wx[4], wy[4];
        cubic_w(tx, wx);
        cubic_w(ty, wy);
        __half2 wxh[4];
#pragma unroll
        for (int n = 0; n < 4; n++) wxh[n] = __float2half2_rn(wx[n]);

        // hoisted x side: offsets + validity computed once per pixel
        int xoff[4];
        bool xval[4];
#pragma unroll
        for (int n = 0; n < 4; n++) {
            int xx = ix - 1 + n;
            xval[n] = ((unsigned)xx < (unsigned)HP_);
            int xs = min(max(xx - P_, 0), W_ - 1);
            xoff[n] = xs * C_;
        }

        const __half* base = g_tin_h + (size_t)b * (H_ * W_ * C_) + lane4 * 8;
#pragma unroll
        for (int m = 0; m < 4; m++) {
            int yy = iy - 1 + m;
            if ((unsigned)yy < (unsigned)HP_) {
                int ys = min(max(yy - P_, 0), H_ - 1);
                const __half* row = base + ys * (W_ * C_);
                __half2 r0 = __float2half2_rn(0.f), r1 = r0, r2 = r0, r3 = r0;

                // stage taps 0-1, consume, stage taps 2-3, consume
                {
                    uint4 va, vb;
                    if (xval[0]) va = __ldg((const uint4*)(row + xoff[0]));
                    if (xval[1]) vb = __ldg((const uint4*)(row + xoff[1]));
                    if (xval[0]) {
                        r0 = __hfma2(*(const __half2*)&va.x, wxh[0], r0);
                        r1 = __hfma2(*(const __half2*)&va.y, wxh[0], r1);
                        r2 = __hfma2(*(const __half2*)&va.z, wxh[0], r2);
                        r3 = __hfma2(*(const __half2*)&va.w, wxh[0], r3);
                    }
                    if (xval[1]) {
                        r0 = __hfma2(*(const __half2*)&vb.x, wxh[1], r0);
                        r1 = __hfma2(*(const __half2*)&vb.y, wxh[1], r1);
                        r2 = __hfma2(*(const __half2*)&vb.z, wxh[1], r2);
                        r3 = __hfma2(*(const __half2*)&vb.w, wxh[1], r3);
                    }
                }
                {
                    uint4 va, vb;
                    if (xval[2]) va = __ldg((const uint4*)(row + xoff[2]));
                    if (xval[3]) vb = __ldg((const uint4*)(row + xoff[3]));
                    if (xval[2]) {
                        r0 = __hfma2(*(const __half2*)&va.x, wxh[2], r0);
                        r1 = __hfma2(*(const __half2*)&va.y, wxh[2], r1);
                        r2 = __hfma2(*(const __half2*)&va.z, wxh[2], r2);
                        r3 = __hfma2(*(const __half2*)&va.w, wxh[2], r3);
                    }
                    if (xval[3]) {
                        r0 = __hfma2(*(const __half2*)&vb.x, wxh[3], r0);
                        r1 = __hfma2(*(const __half2*)&vb.y, wxh[3], r1);
                        r2 = __hfma2(*(const __half2*)&vb.z, wxh[3], r2);
                        r3 = __hfma2(*(const __half2*)&vb.w, wxh[3], r3);
                    }
                }

                float wym = wy[m];
                float2 f01 = __half22float2(r0);
                float2 f23 = __half22float2(r1);
                float2 f45 = __half22float2(r2);
                float2 f67 = __half22float2(r3);
                a0 += wym * f01.x;  a1 += wym * f01.y;
                a2 += wym * f23.x;  a3 += wym * f23.y;
                a4 += wym * f45.x;  a5 += wym * f45.y;
                a6 += wym * f67.x;  a7 += wym * f67.y;
            }
        }
    }

    // s[channel][pixel]; write bank = 8*lane4 + k + pix (+8*warp) mod 32:
    // all 32 distinct -> conflict-free.
    float acc[8] = {a0, a1, a2, a3, a4, a5, a6, a7};
#pragma unroll
    for (int k = 0; k < 8; k++) s[8 * lane4 + k][p] = acc[k];
    __syncthreads();

    // warp w stores channels {w, w+8, w+16, w+24}: 64 contiguous floats each
    // (2 x 128B STG). Read bank = cc + q mod 32: conflict-free.
#pragma unroll
    for (int q = 0; q < 4; q++) {
        int cc = warp + q * 8;
        float* orow = out + (((b * C_ + cc) * H_) + i) * W_ + j0;
        orow[lane]      = s[cc][lane];
        orow[lane + 32] = s[cc][lane + 32];
    }
}

extern "C" void kernel_launch(void* const* d_in, const int* in_sizes, int n_in,
                              void* d_out, int out_size) {
    const float* input = (const float*)d_in[0];   // [8,32,256,256]
    const float* flow  = (const float*)d_in[1];   // [8,2,64,64]
    float* out = (float*)d_out;                   // [8,32,256,256]

    prep_kernel<<<TR_BLOCKS_ + CO_BLOCKS_, 256>>>(input, flow);
    {
        dim3 grid(W_ / GPX_, H_, B_);
        gather_kernel<<<grid, 256>>>(out);
    }
}